// round 2
// baseline (speedup 1.0000x reference)
#include <cuda_runtime.h>

#define IND   128
#define HID   64
#define HEADS 4
#define NEG   0.2f

#define NMAX  50000
#define EMAX  800000

// ---------------- scratch (device globals; no allocation allowed) ----------
static __device__ float    g_xw  [NMAX * HID];            // x @ W_gcn
static __device__ float    g_deg [NMAX];
static __device__ float    g_dinv[NMAX];
static __device__ float    g_gcn [NMAX * HID];            // GCN aggregate (pre-bias/relu)
static __device__ float    g_xl  [NMAX * HEADS * HID];    // lin_l(h)
static __device__ float    g_xr  [NMAX * HEADS * HID];    // lin_r(h)
static __device__ float    g_lg  [(EMAX + NMAX) * HEADS]; // logits, then p
static __device__ unsigned g_mx  [NMAX * HEADS];          // encoded running max
static __device__ float    g_den [NMAX * HEADS];          // softmax denom
static __device__ float    g_agg [NMAX * HEADS * HID];    // GAT aggregate

// ---------------- helpers ----------------
__device__ __forceinline__ unsigned enc_f(float f) {
    unsigned u = __float_as_uint(f);
    return (u & 0x80000000u) ? ~u : (u ^ 0x80000000u);   // order-preserving
}
__device__ __forceinline__ float dec_f(unsigned u) {
    return (u & 0x80000000u) ? __uint_as_float(u ^ 0x80000000u)
                             : __uint_as_float(~u);
}
__device__ __forceinline__ float lrelu(float z) { return z > 0.f ? z : NEG * z; }

__device__ __forceinline__ void red_add_f4(float* p, float4 v) {
    asm volatile("red.global.add.v4.f32 [%0], {%1,%2,%3,%4};"
                 :: "l"(__cvta_generic_to_global(p)),
                    "f"(v.x), "f"(v.y), "f"(v.z), "f"(v.w)
                 : "memory");
}

// ---------------- init ----------------
__global__ void k_init(int n) {
    int idx = blockIdx.x * blockDim.x + threadIdx.x;
    if (idx < n * HEADS * HID) g_agg[idx] = 0.f;
    if (idx < n * HEADS) { g_den[idx] = 0.f; g_mx[idx] = 0u; }
    if (idx < n) g_deg[idx] = 1.0f;   // self-loop contribution to degree
}

// ---------------- degree ----------------
__global__ void k_deg(const int* __restrict__ dst, int e) {
    int i = blockIdx.x * blockDim.x + threadIdx.x;
    if (i < e) atomicAdd(&g_deg[dst[i]], 1.0f);
}

// ---------------- GEMM1: g_xw = x @ W_gcn  ([n,128]x[128,64]) --------------
__global__ void k_gemm1(const float* __restrict__ X, const float* __restrict__ W, int n) {
    __shared__ float xs[64 * 68];   // 64 rows x 64 k (pad 68)
    __shared__ float ws[64 * 64];   // 64 k x 64 cols
    int tid = threadIdx.x;
    int tx = tid & 15, ty = tid >> 4;
    int row0 = blockIdx.x * 64;
    float acc[4][4] = {};

    for (int kc = 0; kc < IND; kc += 64) {
        #pragma unroll
        for (int i = 0; i < 4; i++) {
            int li = tid + i * 256;        // float4 slot 0..1023
            int r  = li >> 4;
            int k4 = li & 15;
            float4 v = make_float4(0.f, 0.f, 0.f, 0.f);
            if (row0 + r < n)
                v = *(const float4*)&X[(size_t)(row0 + r) * IND + kc + k4 * 4];
            *(float4*)&xs[r * 68 + k4 * 4] = v;
        }
        #pragma unroll
        for (int i = 0; i < 4; i++) {
            int li = tid + i * 256;
            int k  = li >> 4;
            int c4 = li & 15;
            *(float4*)&ws[k * 64 + c4 * 4] = *(const float4*)&W[(kc + k) * HID + c4 * 4];
        }
        __syncthreads();
        #pragma unroll 16
        for (int k = 0; k < 64; k++) {
            float4 wv = *(float4*)&ws[k * 64 + tx * 4];
            #pragma unroll
            for (int j = 0; j < 4; j++) {
                float a = xs[(ty * 4 + j) * 68 + k];
                acc[j][0] += a * wv.x; acc[j][1] += a * wv.y;
                acc[j][2] += a * wv.z; acc[j][3] += a * wv.w;
            }
        }
        __syncthreads();
    }
    #pragma unroll
    for (int j = 0; j < 4; j++) {
        int r = row0 + ty * 4 + j;
        if (r < n)
            *(float4*)&g_xw[r * HID + tx * 4] =
                make_float4(acc[j][0], acc[j][1], acc[j][2], acc[j][3]);
    }
}

// ---------------- dinv + self-loop term of GCN -----------------------------
__global__ void k_self(int n) {
    int idx = blockIdx.x * blockDim.x + threadIdx.x;
    if (idx >= n * HID) return;
    int i = idx >> 6;
    float dv = rsqrtf(g_deg[i]);
    if ((idx & 63) == 0) g_dinv[i] = dv;
    g_gcn[idx] = g_xw[idx] * dv * dv;
}

// ---------------- GCN edge scatter (16 threads / edge) ---------------------
__global__ void k_gcn_edge(const int* __restrict__ src, const int* __restrict__ dst, int e) {
    int t = blockIdx.x * blockDim.x + threadIdx.x;
    int edge = t >> 4;
    if (edge >= e) return;
    int lane = t & 15;
    int s = src[edge], d = dst[edge];
    float w = g_dinv[s] * g_dinv[d];
    float4 v = *(const float4*)&g_xw[s * HID + lane * 4];
    v.x *= w; v.y *= w; v.z *= w; v.w *= w;
    red_add_f4(&g_gcn[d * HID + lane * 4], v);
}

// ---------------- GEMM2: xl/xr = relu(gcn+b_gcn) @ W_{l,r} + b_{l,r} -------
__global__ void k_gemm2(const float* __restrict__ Wl, const float* __restrict__ bl,
                        const float* __restrict__ Wr, const float* __restrict__ br,
                        const float* __restrict__ bg, int n) {
    __shared__ float as_[64 * 68];
    __shared__ float ws [64 * 64];
    int tid = threadIdx.x;
    int tx = tid & 15, ty = tid >> 4;
    int row0 = blockIdx.x * 64;
    int mat  = blockIdx.y >> 2;          // 0 -> L, 1 -> R
    int c0   = (blockIdx.y & 3) * 64;    // column tile of 256
    const float* W = mat ? Wr : Wl;
    const float* b = mat ? br : bl;
    float* OUT = mat ? g_xr : g_xl;

    #pragma unroll
    for (int i = 0; i < 4; i++) {
        int li = tid + i * 256;
        int r  = li >> 4;
        int k4 = li & 15;
        float4 v = make_float4(0.f, 0.f, 0.f, 0.f);
        if (row0 + r < n) {
            float4 g  = *(const float4*)&g_gcn[(size_t)(row0 + r) * HID + k4 * 4];
            float4 bb = *(const float4*)&bg[k4 * 4];
            v.x = fmaxf(g.x + bb.x, 0.f); v.y = fmaxf(g.y + bb.y, 0.f);
            v.z = fmaxf(g.z + bb.z, 0.f); v.w = fmaxf(g.w + bb.w, 0.f);
        }
        *(float4*)&as_[r * 68 + k4 * 4] = v;
    }
    #pragma unroll
    for (int i = 0; i < 4; i++) {
        int li = tid + i * 256;
        int k  = li >> 4;
        int c4 = li & 15;
        *(float4*)&ws[k * 64 + c4 * 4] = *(const float4*)&W[k * (HEADS * HID) + c0 + c4 * 4];
    }
    __syncthreads();

    float acc[4][4] = {};
    #pragma unroll 16
    for (int k = 0; k < 64; k++) {
        float4 wv = *(float4*)&ws[k * 64 + tx * 4];
        #pragma unroll
        for (int j = 0; j < 4; j++) {
            float a = as_[(ty * 4 + j) * 68 + k];
            acc[j][0] += a * wv.x; acc[j][1] += a * wv.y;
            acc[j][2] += a * wv.z; acc[j][3] += a * wv.w;
        }
    }
    float4 bv = *(const float4*)&b[c0 + tx * 4];
    #pragma unroll
    for (int j = 0; j < 4; j++) {
        int r = row0 + ty * 4 + j;
        if (r < n)
            *(float4*)&OUT[(size_t)r * (HEADS * HID) + c0 + tx * 4] =
                make_float4(acc[j][0] + bv.x, acc[j][1] + bv.y,
                            acc[j][2] + bv.z, acc[j][3] + bv.w);
    }
}

// ---------------- GATv2 logits (warp / edge) -------------------------------
__global__ void k_logits(const int* __restrict__ src, const int* __restrict__ dst,
                         int e, int n, const float* __restrict__ att) {
    __shared__ float atts[HEADS * HID];
    atts[threadIdx.x] = att[threadIdx.x];     // blockDim == 256 == HEADS*HID
    __syncthreads();

    int gw   = (blockIdx.x * blockDim.x + threadIdx.x) >> 5;
    int lane = threadIdx.x & 31;
    if (gw >= e + n) return;
    int s, d;
    if (gw < e) { s = src[gw]; d = dst[gw]; } else { s = d = gw - e; }

    int head = lane >> 3, j = lane & 7;
    int off = head * HID + j * 8;
    float4 a0 = *(const float4*)&g_xl[(size_t)s * 256 + off];
    float4 a1 = *(const float4*)&g_xl[(size_t)s * 256 + off + 4];
    float4 b0 = *(const float4*)&g_xr[(size_t)d * 256 + off];
    float4 b1 = *(const float4*)&g_xr[(size_t)d * 256 + off + 4];
    float4 w0 = *(const float4*)&atts[off];
    float4 w1 = *(const float4*)&atts[off + 4];

    float acc = w0.x * lrelu(a0.x + b0.x) + w0.y * lrelu(a0.y + b0.y)
              + w0.z * lrelu(a0.z + b0.z) + w0.w * lrelu(a0.w + b0.w)
              + w1.x * lrelu(a1.x + b1.x) + w1.y * lrelu(a1.y + b1.y)
              + w1.z * lrelu(a1.z + b1.z) + w1.w * lrelu(a1.w + b1.w);

    acc += __shfl_xor_sync(0xffffffffu, acc, 1);
    acc += __shfl_xor_sync(0xffffffffu, acc, 2);
    acc += __shfl_xor_sync(0xffffffffu, acc, 4);
    if (j == 0) {
        g_lg[gw * HEADS + head] = acc;
        atomicMax(&g_mx[d * HEADS + head], enc_f(acc));
    }
}

// ---------------- p = exp(logit - m), denom --------------------------------
__global__ void k_p(const int* __restrict__ dst, int e, int n) {
    int idx = blockIdx.x * blockDim.x + threadIdx.x;
    if (idx >= (e + n) * HEADS) return;
    int edge = idx >> 2, h = idx & 3;
    int d = (edge < e) ? dst[edge] : (edge - e);
    float m = dec_f(g_mx[d * HEADS + h]);
    float p = __expf(g_lg[idx] - m);
    g_lg[idx] = p;
    atomicAdd(&g_den[d * HEADS + h], p);
}

// ---------------- GAT aggregate (warp / edge) ------------------------------
__global__ void k_agg(const int* __restrict__ src, const int* __restrict__ dst,
                      int e, int n) {
    int gw   = (blockIdx.x * blockDim.x + threadIdx.x) >> 5;
    int lane = threadIdx.x & 31;
    if (gw >= e + n) return;
    int s, d;
    if (gw < e) { s = src[gw]; d = dst[gw]; } else { s = d = gw - e; }

    int head = lane >> 3;                       // lane covers floats [lane*8, lane*8+8)
    float alpha = g_lg[gw * HEADS + head] / g_den[d * HEADS + head];
    int off = lane * 8;
    float4 v0 = *(const float4*)&g_xl[(size_t)s * 256 + off];
    float4 v1 = *(const float4*)&g_xl[(size_t)s * 256 + off + 4];
    v0.x *= alpha; v0.y *= alpha; v0.z *= alpha; v0.w *= alpha;
    v1.x *= alpha; v1.y *= alpha; v1.z *= alpha; v1.w *= alpha;
    red_add_f4(&g_agg[(size_t)d * 256 + off],     v0);
    red_add_f4(&g_agg[(size_t)d * 256 + off + 4], v1);
}

// ---------------- head-mean + bias + relu + output linear ------------------
__global__ void k_final(const float* __restrict__ bgat, const float* __restrict__ Wlin,
                        const float* __restrict__ blin, float* __restrict__ out, int n) {
    int gw   = (blockIdx.x * blockDim.x + threadIdx.x) >> 5;
    int lane = threadIdx.x & 31;
    if (gw >= n) return;
    const float* p = &g_agg[(size_t)gw * 256];
    float acc = 0.f;
    #pragma unroll
    for (int c = lane; c < HID; c += 32) {
        float sh = p[c] + p[64 + c] + p[128 + c] + p[192 + c];
        float hv = fmaxf(0.25f * sh + bgat[c], 0.f);
        acc += hv * Wlin[c];
    }
    #pragma unroll
    for (int o = 16; o; o >>= 1) acc += __shfl_xor_sync(0xffffffffu, acc, o);
    if (lane == 0) out[gw] = acc + blin[0];
}

// ---------------- launch ----------------
extern "C" void kernel_launch(void* const* d_in, const int* in_sizes, int n_in,
                              void* d_out, int out_size) {
    const float* x    = (const float*)d_in[0];
    const int*   ei   = (const int*)d_in[1];
    // d_in[2] = edge_attr (unused by reference)
    const float* Wg   = (const float*)d_in[3];
    const float* bg   = (const float*)d_in[4];
    const float* Wl   = (const float*)d_in[5];
    const float* bl   = (const float*)d_in[6];
    const float* Wr   = (const float*)d_in[7];
    const float* br   = (const float*)d_in[8];
    const float* att  = (const float*)d_in[9];
    const float* bgat = (const float*)d_in[10];
    const float* Wlin = (const float*)d_in[11];
    const float* blin = (const float*)d_in[12];
    float* out = (float*)d_out;

    int n = in_sizes[0] / IND;       // 50000
    int e = in_sizes[1] / 2;         // 800000
    const int* src = ei;
    const int* dst = ei + e;
    int ep = e + n;                  // edges incl. self loops

    k_init    <<<(n * 256 + 255) / 256, 256>>>(n);
    k_deg     <<<(e + 255) / 256, 256>>>(dst, e);
    k_gemm1   <<<(n + 63) / 64, 256>>>(x, Wg, n);
    k_self    <<<(n * HID + 255) / 256, 256>>>(n);
    k_gcn_edge<<<(e * 16 + 255) / 256, 256>>>(src, dst, e);

    dim3 g2((n + 63) / 64, 8);
    k_gemm2   <<<g2, 256>>>(Wl, bl, Wr, br, bg, n);

    k_logits  <<<(ep * 32 + 255) / 256, 256>>>(src, dst, e, n, att);
    k_p       <<<(ep * 4 + 255) / 256, 256>>>(dst, e, n);
    k_agg     <<<(ep * 32 + 255) / 256, 256>>>(src, dst, e, n);
    k_final   <<<(n * 32 + 255) / 256, 256>>>(bgat, Wlin, blin, out, n);
}

// round 3
// speedup vs baseline: 2.4641x; 2.4641x over previous
#include <cuda_runtime.h>

#define IND   128
#define HID   64
#define HEADS 4
#define NEG   0.2f

#define NMAX  50000
#define EMAX  800000

// ---------------- scratch (device globals; no allocation allowed) ----------
static __device__ int   g_cnt [NMAX];            // dst histogram
static __device__ int   g_offs[NMAX + 1];        // CSR row offsets
static __device__ int   g_cur [NMAX];            // fill cursors
static __device__ int   g_bsum[512];             // scan block sums
static __device__ int   g_csrc[EMAX];            // CSR src ids (grouped by dst)
static __device__ float g_dinv[NMAX];
static __device__ float g_xw  [NMAX * HID];      // x @ W_gcn
static __device__ float g_h   [NMAX * HID];      // relu(GCN out)
static __device__ float g_xl  [NMAX * HEADS * HID];
static __device__ float g_xr  [NMAX * HEADS * HID];

__device__ __forceinline__ float lrelu(float z) { return z > 0.f ? z : NEG * z; }

// ---------------- init ----------------
__global__ void k_init(int n) {
    int i = blockIdx.x * blockDim.x + threadIdx.x;
    if (i < n) g_cnt[i] = 0;
}

__global__ void k_hist(const int* __restrict__ dst, int e) {
    int i = blockIdx.x * blockDim.x + threadIdx.x;
    if (i < e) atomicAdd(&g_cnt[dst[i]], 1);
}

// ---------------- scan: exclusive prefix over g_cnt -> g_offs --------------
__global__ void k_scan1(int n) {
    __shared__ int sh[256];
    int i = blockIdx.x * 256 + threadIdx.x;
    int v = (i < n) ? g_cnt[i] : 0;
    sh[threadIdx.x] = v;
    __syncthreads();
    #pragma unroll
    for (int off = 1; off < 256; off <<= 1) {
        int t = (threadIdx.x >= off) ? sh[threadIdx.x - off] : 0;
        __syncthreads();
        sh[threadIdx.x] += t;
        __syncthreads();
    }
    if (i < n) g_offs[i] = sh[threadIdx.x] - v;          // block-local exclusive
    if (threadIdx.x == 255) g_bsum[blockIdx.x] = sh[255];
}

__global__ void k_scan2(int nblk) {
    __shared__ int sh[256];
    __shared__ int carry;
    if (threadIdx.x == 0) carry = 0;
    __syncthreads();
    for (int base = 0; base < nblk; base += 256) {
        int i = base + threadIdx.x;
        int v = (i < nblk) ? g_bsum[i] : 0;
        sh[threadIdx.x] = v;
        __syncthreads();
        #pragma unroll
        for (int off = 1; off < 256; off <<= 1) {
            int t = (threadIdx.x >= off) ? sh[threadIdx.x - off] : 0;
            __syncthreads();
            sh[threadIdx.x] += t;
            __syncthreads();
        }
        if (i < nblk) g_bsum[i] = sh[threadIdx.x] - v + carry;
        int tot = sh[255];
        __syncthreads();
        if (threadIdx.x == 0) carry += tot;
        __syncthreads();
    }
}

__global__ void k_scan3(int n, int e) {
    int i = blockIdx.x * blockDim.x + threadIdx.x;
    if (i < n) {
        int off = g_offs[i] + g_bsum[i >> 8];
        g_offs[i] = off;
        g_cur[i]  = off;
        g_dinv[i] = rsqrtf((float)g_cnt[i] + 1.0f);      // +1 self-loop
    }
    if (i == 0) g_offs[n] = e;
}

__global__ void k_fill(const int* __restrict__ src, const int* __restrict__ dst, int e) {
    int i = blockIdx.x * blockDim.x + threadIdx.x;
    if (i >= e) return;
    int d = dst[i];
    int pos = atomicAdd(&g_cur[d], 1);
    g_csrc[pos] = src[i];
}

// ---------------- GEMM1: g_xw = x @ W_gcn ----------------------------------
__global__ void k_gemm1(const float* __restrict__ X, const float* __restrict__ W, int n) {
    __shared__ float xs[64 * 68];
    __shared__ float ws[64 * 64];
    int tid = threadIdx.x;
    int tx = tid & 15, ty = tid >> 4;
    int row0 = blockIdx.x * 64;
    float acc[4][4] = {};

    for (int kc = 0; kc < IND; kc += 64) {
        #pragma unroll
        for (int i = 0; i < 4; i++) {
            int li = tid + i * 256;
            int r = li >> 4, k4 = li & 15;
            float4 v = make_float4(0.f, 0.f, 0.f, 0.f);
            if (row0 + r < n)
                v = *(const float4*)&X[(size_t)(row0 + r) * IND + kc + k4 * 4];
            *(float4*)&xs[r * 68 + k4 * 4] = v;
        }
        #pragma unroll
        for (int i = 0; i < 4; i++) {
            int li = tid + i * 256;
            int k = li >> 4, c4 = li & 15;
            *(float4*)&ws[k * 64 + c4 * 4] = *(const float4*)&W[(kc + k) * HID + c4 * 4];
        }
        __syncthreads();
        #pragma unroll 16
        for (int k = 0; k < 64; k++) {
            float4 wv = *(float4*)&ws[k * 64 + tx * 4];
            #pragma unroll
            for (int j = 0; j < 4; j++) {
                float a = xs[(ty * 4 + j) * 68 + k];
                acc[j][0] += a * wv.x; acc[j][1] += a * wv.y;
                acc[j][2] += a * wv.z; acc[j][3] += a * wv.w;
            }
        }
        __syncthreads();
    }
    #pragma unroll
    for (int j = 0; j < 4; j++) {
        int r = row0 + ty * 4 + j;
        if (r < n)
            *(float4*)&g_xw[r * HID + tx * 4] =
                make_float4(acc[j][0], acc[j][1], acc[j][2], acc[j][3]);
    }
}

// ---------------- GCN via CSR: warp per dst node ---------------------------
__global__ void k_gcn(const float* __restrict__ bg, int n) {
    int node = (blockIdx.x * blockDim.x + threadIdx.x) >> 5;
    int lane = threadIdx.x & 31;
    if (node >= n) return;
    int r0 = g_offs[node], r1 = g_offs[node + 1];

    float2 sum = make_float2(0.f, 0.f);
    int j = r0;
    for (; j + 1 < r1; j += 2) {
        int s0 = g_csrc[j], s1 = g_csrc[j + 1];
        float w0 = g_dinv[s0], w1 = g_dinv[s1];
        float2 v0 = *(const float2*)&g_xw[(size_t)s0 * HID + lane * 2];
        float2 v1 = *(const float2*)&g_xw[(size_t)s1 * HID + lane * 2];
        sum.x += w0 * v0.x + w1 * v1.x;
        sum.y += w0 * v0.y + w1 * v1.y;
    }
    if (j < r1) {
        int s0 = g_csrc[j];
        float w0 = g_dinv[s0];
        float2 v0 = *(const float2*)&g_xw[(size_t)s0 * HID + lane * 2];
        sum.x += w0 * v0.x; sum.y += w0 * v0.y;
    }
    float wd = g_dinv[node];
    float2 sv = *(const float2*)&g_xw[(size_t)node * HID + lane * 2];
    sum.x = (sum.x + wd * sv.x) * wd;
    sum.y = (sum.y + wd * sv.y) * wd;
    float2 bb = *(const float2*)&bg[lane * 2];
    float2 h;
    h.x = fmaxf(sum.x + bb.x, 0.f);
    h.y = fmaxf(sum.y + bb.y, 0.f);
    *(float2*)&g_h[(size_t)node * HID + lane * 2] = h;
}

// ---------------- GEMM2: xl/xr = g_h @ W_{l,r} + b -------------------------
__global__ void k_gemm2(const float* __restrict__ Wl, const float* __restrict__ bl,
                        const float* __restrict__ Wr, const float* __restrict__ br,
                        int n) {
    __shared__ float as_[64 * 68];
    __shared__ float ws [64 * 64];
    int tid = threadIdx.x;
    int tx = tid & 15, ty = tid >> 4;
    int row0 = blockIdx.x * 64;
    int mat  = blockIdx.y >> 2;
    int c0   = (blockIdx.y & 3) * 64;
    const float* W = mat ? Wr : Wl;
    const float* b = mat ? br : bl;
    float* OUT = mat ? g_xr : g_xl;

    #pragma unroll
    for (int i = 0; i < 4; i++) {
        int li = tid + i * 256;
        int r = li >> 4, k4 = li & 15;
        float4 v = make_float4(0.f, 0.f, 0.f, 0.f);
        if (row0 + r < n)
            v = *(const float4*)&g_h[(size_t)(row0 + r) * HID + k4 * 4];
        *(float4*)&as_[r * 68 + k4 * 4] = v;
    }
    #pragma unroll
    for (int i = 0; i < 4; i++) {
        int li = tid + i * 256;
        int k = li >> 4, c4 = li & 15;
        *(float4*)&ws[k * 64 + c4 * 4] = *(const float4*)&W[k * (HEADS * HID) + c0 + c4 * 4];
    }
    __syncthreads();

    float acc[4][4] = {};
    #pragma unroll 16
    for (int k = 0; k < 64; k++) {
        float4 wv = *(float4*)&ws[k * 64 + tx * 4];
        #pragma unroll
        for (int j = 0; j < 4; j++) {
            float a = as_[(ty * 4 + j) * 68 + k];
            acc[j][0] += a * wv.x; acc[j][1] += a * wv.y;
            acc[j][2] += a * wv.z; acc[j][3] += a * wv.w;
        }
    }
    float4 bv = *(const float4*)&b[c0 + tx * 4];
    #pragma unroll
    for (int j = 0; j < 4; j++) {
        int r = row0 + ty * 4 + j;
        if (r < n)
            *(float4*)&OUT[(size_t)r * (HEADS * HID) + c0 + tx * 4] =
                make_float4(acc[j][0] + bv.x, acc[j][1] + bv.y,
                            acc[j][2] + bv.z, acc[j][3] + bv.w);
    }
}

// ---------------- Fused GATv2 + mean + relu + linear: warp per dst node ----
// lane = head*8 + j; lane covers elements [head*64 + j*8, +8) of each 256-vec.
__global__ void k_gat(const float* __restrict__ att, const float* __restrict__ bgat,
                      const float* __restrict__ Wlin, const float* __restrict__ blin,
                      float* __restrict__ out, int n) {
    int node = (blockIdx.x * blockDim.x + threadIdx.x) >> 5;
    int lane = threadIdx.x & 31;
    if (node >= n) return;
    int off = lane * 8;

    float4 at0 = *(const float4*)&att[off];
    float4 at1 = *(const float4*)&att[off + 4];
    float4 xr0 = *(const float4*)&g_xr[(size_t)node * 256 + off];
    float4 xr1 = *(const float4*)&g_xr[(size_t)node * 256 + off + 4];

    // self edge initializes online state
    float4 a0 = *(const float4*)&g_xl[(size_t)node * 256 + off];
    float4 a1 = *(const float4*)&g_xl[(size_t)node * 256 + off + 4];
    float z = at0.x * lrelu(a0.x + xr0.x) + at0.y * lrelu(a0.y + xr0.y)
            + at0.z * lrelu(a0.z + xr0.z) + at0.w * lrelu(a0.w + xr0.w)
            + at1.x * lrelu(a1.x + xr1.x) + at1.y * lrelu(a1.y + xr1.y)
            + at1.z * lrelu(a1.z + xr1.z) + at1.w * lrelu(a1.w + xr1.w);
    z += __shfl_xor_sync(0xffffffffu, z, 1);
    z += __shfl_xor_sync(0xffffffffu, z, 2);
    z += __shfl_xor_sync(0xffffffffu, z, 4);
    float m = z;          // running max
    float den = 1.f;      // exp(z - m) = 1

    int r0 = g_offs[node], r1 = g_offs[node + 1];
    for (int j = r0; j < r1; j++) {
        int s = g_csrc[j];
        float4 v0 = *(const float4*)&g_xl[(size_t)s * 256 + off];
        float4 v1 = *(const float4*)&g_xl[(size_t)s * 256 + off + 4];
        float zz = at0.x * lrelu(v0.x + xr0.x) + at0.y * lrelu(v0.y + xr0.y)
                 + at0.z * lrelu(v0.z + xr0.z) + at0.w * lrelu(v0.w + xr0.w)
                 + at1.x * lrelu(v1.x + xr1.x) + at1.y * lrelu(v1.y + xr1.y)
                 + at1.z * lrelu(v1.z + xr1.z) + at1.w * lrelu(v1.w + xr1.w);
        zz += __shfl_xor_sync(0xffffffffu, zz, 1);
        zz += __shfl_xor_sync(0xffffffffu, zz, 2);
        zz += __shfl_xor_sync(0xffffffffu, zz, 4);

        float mn = fmaxf(m, zz);
        float sc = __expf(m - mn);
        float p  = __expf(zz - mn);
        den = den * sc + p;
        a0.x = a0.x * sc + p * v0.x;  a0.y = a0.y * sc + p * v0.y;
        a0.z = a0.z * sc + p * v0.z;  a0.w = a0.w * sc + p * v0.w;
        a1.x = a1.x * sc + p * v1.x;  a1.y = a1.y * sc + p * v1.y;
        a1.z = a1.z * sc + p * v1.z;  a1.w = a1.w * sc + p * v1.w;
        m = mn;
    }

    float inv = __frcp_rn(den);
    float v[8] = { a0.x * inv, a0.y * inv, a0.z * inv, a0.w * inv,
                   a1.x * inv, a1.y * inv, a1.z * inv, a1.w * inv };

    // sum across heads (lanes differing in bits 3,4)
    #pragma unroll
    for (int k = 0; k < 8; k++) {
        v[k] += __shfl_xor_sync(0xffffffffu, v[k], 8);
        v[k] += __shfl_xor_sync(0xffffffffu, v[k], 16);
    }

    // epilogue: mean, +bgat, relu, dot with Wlin
    int c = (lane & 7) * 8;
    float sc = 0.f;
    #pragma unroll
    for (int k = 0; k < 8; k++) {
        float hv = fmaxf(0.25f * v[k] + __ldg(&bgat[c + k]), 0.f);
        sc += hv * __ldg(&Wlin[c + k]);
    }
    sc += __shfl_xor_sync(0xffffffffu, sc, 1);
    sc += __shfl_xor_sync(0xffffffffu, sc, 2);
    sc += __shfl_xor_sync(0xffffffffu, sc, 4);
    if (lane == 0) out[node] = sc + __ldg(&blin[0]);
}

// ---------------- launch ----------------
extern "C" void kernel_launch(void* const* d_in, const int* in_sizes, int n_in,
                              void* d_out, int out_size) {
    const float* x    = (const float*)d_in[0];
    const int*   ei   = (const int*)d_in[1];
    // d_in[2] = edge_attr (unused by reference)
    const float* Wg   = (const float*)d_in[3];
    const float* bg   = (const float*)d_in[4];
    const float* Wl   = (const float*)d_in[5];
    const float* bl   = (const float*)d_in[6];
    const float* Wr   = (const float*)d_in[7];
    const float* br   = (const float*)d_in[8];
    const float* att  = (const float*)d_in[9];
    const float* bgat = (const float*)d_in[10];
    const float* Wlin = (const float*)d_in[11];
    const float* blin = (const float*)d_in[12];
    float* out = (float*)d_out;

    int n = in_sizes[0] / IND;       // 50000
    int e = in_sizes[1] / 2;         // 800000
    const int* src = ei;
    const int* dst = ei + e;
    int nblk = (n + 255) / 256;

    k_init <<<(n + 255) / 256, 256>>>(n);
    k_hist <<<(e + 255) / 256, 256>>>(dst, e);
    k_scan1<<<nblk, 256>>>(n);
    k_scan2<<<1, 256>>>(nblk);
    k_scan3<<<(n + 255) / 256, 256>>>(n, e);
    k_fill <<<(e + 255) / 256, 256>>>(src, dst, e);

    k_gemm1<<<(n + 63) / 64, 256>>>(x, Wg, n);
    k_gcn  <<<(n * 32 + 255) / 256, 256>>>(bg, n);

    dim3 g2((n + 63) / 64, 8);
    k_gemm2<<<g2, 256>>>(Wl, bl, Wr, br, n);

    k_gat  <<<(n * 32 + 255) / 256, 256>>>(att, bgat, Wlin, blin, out, n);
}

// round 4
// speedup vs baseline: 2.4914x; 1.0111x over previous
#include <cuda_runtime.h>

#define IND   128
#define HID   64
#define HEADS 4
#define NEG   0.2f

#define NMAX  50000
#define EMAX  800000
#define FULLM 0xffffffffu

// ---------------- scratch (device globals; no allocation allowed) ----------
static __device__ int   g_cnt [NMAX];            // dst histogram
static __device__ int   g_offs[NMAX + 1];        // CSR row offsets
static __device__ int   g_cur [NMAX];            // fill cursors
static __device__ int   g_bsum[512];             // scan block sums
static __device__ int   g_csrc[EMAX];            // CSR src ids (grouped by dst)
static __device__ float g_dinv[NMAX];
static __device__ float g_xw  [NMAX * HID];      // x @ W_gcn
static __device__ float g_h   [NMAX * HID];      // relu(GCN out)
static __device__ float g_xl  [NMAX * HEADS * HID];
static __device__ float g_xr  [NMAX * HEADS * HID];

__device__ __forceinline__ float lrelu(float z) { return z > 0.f ? z : NEG * z; }

// ---------------- CSR build ----------------
__global__ void k_init(int n) {
    int i = blockIdx.x * blockDim.x + threadIdx.x;
    if (i < n) g_cnt[i] = 0;
}

__global__ void k_hist(const int* __restrict__ dst, int e) {
    int i = blockIdx.x * blockDim.x + threadIdx.x;
    if (i < e) atomicAdd(&g_cnt[dst[i]], 1);
}

// 1024-thread shuffle scan; 49 blocks for n=50000
__global__ void k_scan1(int n) {
    __shared__ int wsum[32];
    int i = blockIdx.x * 1024 + threadIdx.x;
    int v = (i < n) ? g_cnt[i] : 0;
    int lane = threadIdx.x & 31, wid = threadIdx.x >> 5;
    int x = v;
    #pragma unroll
    for (int o = 1; o < 32; o <<= 1) {
        int t = __shfl_up_sync(FULLM, x, o);
        if (lane >= o) x += t;
    }
    if (lane == 31) wsum[wid] = x;
    __syncthreads();
    if (wid == 0) {
        int s = wsum[lane];
        #pragma unroll
        for (int o = 1; o < 32; o <<= 1) {
            int t = __shfl_up_sync(FULLM, s, o);
            if (lane >= o) s += t;
        }
        wsum[lane] = s;
    }
    __syncthreads();
    int add = wid ? wsum[wid - 1] : 0;
    if (i < n) g_offs[i] = add + x - v;           // exclusive
    if (threadIdx.x == 1023) g_bsum[blockIdx.x] = wsum[31];
}

// single block, 64 threads, nblk <= 64
__global__ void k_scan2(int nblk) {
    __shared__ int sh[64];
    int v = (threadIdx.x < nblk) ? g_bsum[threadIdx.x] : 0;
    sh[threadIdx.x] = v;
    __syncthreads();
    #pragma unroll
    for (int o = 1; o < 64; o <<= 1) {
        int t = (threadIdx.x >= o) ? sh[threadIdx.x - o] : 0;
        __syncthreads();
        sh[threadIdx.x] += t;
        __syncthreads();
    }
    if (threadIdx.x < nblk) g_bsum[threadIdx.x] = sh[threadIdx.x] - v;
}

__global__ void k_scan3(int n, int e) {
    int i = blockIdx.x * blockDim.x + threadIdx.x;
    if (i < n) {
        int off = g_offs[i] + g_bsum[i >> 10];
        g_offs[i] = off;
        g_cur[i]  = off;
        g_dinv[i] = rsqrtf((float)g_cnt[i] + 1.0f);      // +1 self-loop
    }
    if (i == 0) g_offs[n] = e;
}

__global__ void k_fill(const int* __restrict__ src, const int* __restrict__ dst, int e) {
    int i = blockIdx.x * blockDim.x + threadIdx.x;
    if (i >= e) return;
    int d = dst[i];
    int pos = atomicAdd(&g_cur[d], 1);
    g_csrc[pos] = src[i];
}

// ---------------- GEMM1: g_xw = x @ W_gcn ----------------------------------
__global__ void k_gemm1(const float* __restrict__ X, const float* __restrict__ W, int n) {
    __shared__ float xs[64 * 68];
    __shared__ float ws[64 * 64];
    int tid = threadIdx.x;
    int tx = tid & 15, ty = tid >> 4;
    int row0 = blockIdx.x * 64;
    float acc[4][4] = {};

    for (int kc = 0; kc < IND; kc += 64) {
        #pragma unroll
        for (int i = 0; i < 4; i++) {
            int li = tid + i * 256;
            int r = li >> 4, k4 = li & 15;
            float4 v = make_float4(0.f, 0.f, 0.f, 0.f);
            if (row0 + r < n)
                v = *(const float4*)&X[(size_t)(row0 + r) * IND + kc + k4 * 4];
            *(float4*)&xs[r * 68 + k4 * 4] = v;
        }
        #pragma unroll
        for (int i = 0; i < 4; i++) {
            int li = tid + i * 256;
            int k = li >> 4, c4 = li & 15;
            *(float4*)&ws[k * 64 + c4 * 4] = *(const float4*)&W[(kc + k) * HID + c4 * 4];
        }
        __syncthreads();
        #pragma unroll 16
        for (int k = 0; k < 64; k++) {
            float4 wv = *(float4*)&ws[k * 64 + tx * 4];
            #pragma unroll
            for (int j = 0; j < 4; j++) {
                float a = xs[(ty * 4 + j) * 68 + k];
                acc[j][0] += a * wv.x; acc[j][1] += a * wv.y;
                acc[j][2] += a * wv.z; acc[j][3] += a * wv.w;
            }
        }
        __syncthreads();
    }
    #pragma unroll
    for (int j = 0; j < 4; j++) {
        int r = row0 + ty * 4 + j;
        if (r < n)
            *(float4*)&g_xw[r * HID + tx * 4] =
                make_float4(acc[j][0], acc[j][1], acc[j][2], acc[j][3]);
    }
}

// ---------------- GCN via CSR: warp per dst node, 2-edge ILP ---------------
__global__ void k_gcn(const float* __restrict__ bg, int n) {
    int node = (blockIdx.x * blockDim.x + threadIdx.x) >> 5;
    int lane = threadIdx.x & 31;
    if (node >= n) return;
    int r0 = g_offs[node], r1 = g_offs[node + 1];

    float2 sum = make_float2(0.f, 0.f);
    for (int base = r0; base < r1; base += 32) {
        int rem = r1 - base;
        int cnt = rem < 32 ? rem : 32;
        int sidx = 0; float sw = 0.f;
        if (lane < cnt) { sidx = g_csrc[base + lane]; sw = g_dinv[sidx]; }
        int k = 0;
        for (; k + 1 < cnt; k += 2) {
            int   s0 = __shfl_sync(FULLM, sidx, k);
            int   s1 = __shfl_sync(FULLM, sidx, k + 1);
            float w0 = __shfl_sync(FULLM, sw,   k);
            float w1 = __shfl_sync(FULLM, sw,   k + 1);
            float2 v0 = *(const float2*)&g_xw[(size_t)s0 * HID + lane * 2];
            float2 v1 = *(const float2*)&g_xw[(size_t)s1 * HID + lane * 2];
            sum.x += w0 * v0.x + w1 * v1.x;
            sum.y += w0 * v0.y + w1 * v1.y;
        }
        if (k < cnt) {
            int   s0 = __shfl_sync(FULLM, sidx, k);
            float w0 = __shfl_sync(FULLM, sw,   k);
            float2 v0 = *(const float2*)&g_xw[(size_t)s0 * HID + lane * 2];
            sum.x += w0 * v0.x; sum.y += w0 * v0.y;
        }
    }
    float wd = g_dinv[node];
    float2 sv = *(const float2*)&g_xw[(size_t)node * HID + lane * 2];
    sum.x = (sum.x + wd * sv.x) * wd;
    sum.y = (sum.y + wd * sv.y) * wd;
    float2 bb = *(const float2*)&bg[lane * 2];
    float2 h;
    h.x = fmaxf(sum.x + bb.x, 0.f);
    h.y = fmaxf(sum.y + bb.y, 0.f);
    *(float2*)&g_h[(size_t)node * HID + lane * 2] = h;
}

// ---------------- GEMM2: xl/xr = g_h @ W_{l,r} + b -------------------------
__global__ void k_gemm2(const float* __restrict__ Wl, const float* __restrict__ bl,
                        const float* __restrict__ Wr, const float* __restrict__ br,
                        int n) {
    __shared__ float as_[64 * 68];
    __shared__ float ws [64 * 64];
    int tid = threadIdx.x;
    int tx = tid & 15, ty = tid >> 4;
    int row0 = blockIdx.x * 64;
    int mat  = blockIdx.y >> 2;
    int c0   = (blockIdx.y & 3) * 64;
    const float* W = mat ? Wr : Wl;
    const float* b = mat ? br : bl;
    float* OUT = mat ? g_xr : g_xl;

    #pragma unroll
    for (int i = 0; i < 4; i++) {
        int li = tid + i * 256;
        int r = li >> 4, k4 = li & 15;
        float4 v = make_float4(0.f, 0.f, 0.f, 0.f);
        if (row0 + r < n)
            v = *(const float4*)&g_h[(size_t)(row0 + r) * HID + k4 * 4];
        *(float4*)&as_[r * 68 + k4 * 4] = v;
    }
    #pragma unroll
    for (int i = 0; i < 4; i++) {
        int li = tid + i * 256;
        int k = li >> 4, c4 = li & 15;
        *(float4*)&ws[k * 64 + c4 * 4] = *(const float4*)&W[k * (HEADS * HID) + c0 + c4 * 4];
    }
    __syncthreads();

    float acc[4][4] = {};
    #pragma unroll 16
    for (int k = 0; k < 64; k++) {
        float4 wv = *(float4*)&ws[k * 64 + tx * 4];
        #pragma unroll
        for (int j = 0; j < 4; j++) {
            float a = as_[(ty * 4 + j) * 68 + k];
            acc[j][0] += a * wv.x; acc[j][1] += a * wv.y;
            acc[j][2] += a * wv.z; acc[j][3] += a * wv.w;
        }
    }
    float4 bv = *(const float4*)&b[c0 + tx * 4];
    #pragma unroll
    for (int j = 0; j < 4; j++) {
        int r = row0 + ty * 4 + j;
        if (r < n)
            *(float4*)&OUT[(size_t)r * (HEADS * HID) + c0 + tx * 4] =
                make_float4(acc[j][0] + bv.x, acc[j][1] + bv.y,
                            acc[j][2] + bv.z, acc[j][3] + bv.w);
    }
}

// ---------------- Fused GATv2 + mean + relu + linear: warp per dst node ----
// lane covers elements [lane*8, lane*8+8); lanes 8h..8h+7 = head h.
__global__ void k_gat(const float* __restrict__ att, const float* __restrict__ bgat,
                      const float* __restrict__ Wlin, const float* __restrict__ blin,
                      float* __restrict__ out, int n) {
    int node = (blockIdx.x * blockDim.x + threadIdx.x) >> 5;
    int lane = threadIdx.x & 31;
    if (node >= n) return;
    int off = lane * 8;

    float4 at0 = *(const float4*)&att[off];
    float4 at1 = *(const float4*)&att[off + 4];
    float4 xr0 = *(const float4*)&g_xr[(size_t)node * 256 + off];
    float4 xr1 = *(const float4*)&g_xr[(size_t)node * 256 + off + 4];

    // self edge initializes online state
    float4 a0 = *(const float4*)&g_xl[(size_t)node * 256 + off];
    float4 a1 = *(const float4*)&g_xl[(size_t)node * 256 + off + 4];
    float z = at0.x * lrelu(a0.x + xr0.x) + at0.y * lrelu(a0.y + xr0.y)
            + at0.z * lrelu(a0.z + xr0.z) + at0.w * lrelu(a0.w + xr0.w)
            + at1.x * lrelu(a1.x + xr1.x) + at1.y * lrelu(a1.y + xr1.y)
            + at1.z * lrelu(a1.z + xr1.z) + at1.w * lrelu(a1.w + xr1.w);
    z += __shfl_xor_sync(FULLM, z, 1);
    z += __shfl_xor_sync(FULLM, z, 2);
    z += __shfl_xor_sync(FULLM, z, 4);
    float m = z;          // running max (per head group)
    float den = 1.f;      // exp(z - m) = 1

    int r0 = g_offs[node], r1 = g_offs[node + 1];
    for (int base = r0; base < r1; base += 32) {
        int rem = r1 - base;
        int cnt = rem < 32 ? rem : 32;
        int sidx = (lane < cnt) ? g_csrc[base + lane] : 0;
        int k = 0;
        for (; k + 1 < cnt; k += 2) {
            int s0 = __shfl_sync(FULLM, sidx, k);
            int s1 = __shfl_sync(FULLM, sidx, k + 1);
            float4 u0 = *(const float4*)&g_xl[(size_t)s0 * 256 + off];
            float4 u1 = *(const float4*)&g_xl[(size_t)s0 * 256 + off + 4];
            float4 w0 = *(const float4*)&g_xl[(size_t)s1 * 256 + off];
            float4 w1 = *(const float4*)&g_xl[(size_t)s1 * 256 + off + 4];
            float za = at0.x * lrelu(u0.x + xr0.x) + at0.y * lrelu(u0.y + xr0.y)
                     + at0.z * lrelu(u0.z + xr0.z) + at0.w * lrelu(u0.w + xr0.w)
                     + at1.x * lrelu(u1.x + xr1.x) + at1.y * lrelu(u1.y + xr1.y)
                     + at1.z * lrelu(u1.z + xr1.z) + at1.w * lrelu(u1.w + xr1.w);
            float zb = at0.x * lrelu(w0.x + xr0.x) + at0.y * lrelu(w0.y + xr0.y)
                     + at0.z * lrelu(w0.z + xr0.z) + at0.w * lrelu(w0.w + xr0.w)
                     + at1.x * lrelu(w1.x + xr1.x) + at1.y * lrelu(w1.y + xr1.y)
                     + at1.z * lrelu(w1.z + xr1.z) + at1.w * lrelu(w1.w + xr1.w);
            za += __shfl_xor_sync(FULLM, za, 1);
            zb += __shfl_xor_sync(FULLM, zb, 1);
            za += __shfl_xor_sync(FULLM, za, 2);
            zb += __shfl_xor_sync(FULLM, zb, 2);
            za += __shfl_xor_sync(FULLM, za, 4);
            zb += __shfl_xor_sync(FULLM, zb, 4);

            float mn = fmaxf(m, fmaxf(za, zb));
            float pa = __expf(za - mn);
            float pb = __expf(zb - mn);
            if (mn == m) {                      // fast path: no rescale
                den += pa + pb;
                a0.x += pa * u0.x + pb * w0.x;  a0.y += pa * u0.y + pb * w0.y;
                a0.z += pa * u0.z + pb * w0.z;  a0.w += pa * u0.w + pb * w0.w;
                a1.x += pa * u1.x + pb * w1.x;  a1.y += pa * u1.y + pb * w1.y;
                a1.z += pa * u1.z + pb * w1.z;  a1.w += pa * u1.w + pb * w1.w;
            } else {
                float sc = __expf(m - mn);
                den = den * sc + pa + pb;
                a0.x = a0.x * sc + pa * u0.x + pb * w0.x;
                a0.y = a0.y * sc + pa * u0.y + pb * w0.y;
                a0.z = a0.z * sc + pa * u0.z + pb * w0.z;
                a0.w = a0.w * sc + pa * u0.w + pb * w0.w;
                a1.x = a1.x * sc + pa * u1.x + pb * w1.x;
                a1.y = a1.y * sc + pa * u1.y + pb * w1.y;
                a1.z = a1.z * sc + pa * u1.z + pb * w1.z;
                a1.w = a1.w * sc + pa * u1.w + pb * w1.w;
                m = mn;
            }
        }
        if (k < cnt) {
            int s0 = __shfl_sync(FULLM, sidx, k);
            float4 u0 = *(const float4*)&g_xl[(size_t)s0 * 256 + off];
            float4 u1 = *(const float4*)&g_xl[(size_t)s0 * 256 + off + 4];
            float za = at0.x * lrelu(u0.x + xr0.x) + at0.y * lrelu(u0.y + xr0.y)
                     + at0.z * lrelu(u0.z + xr0.z) + at0.w * lrelu(u0.w + xr0.w)
                     + at1.x * lrelu(u1.x + xr1.x) + at1.y * lrelu(u1.y + xr1.y)
                     + at1.z * lrelu(u1.z + xr1.z) + at1.w * lrelu(u1.w + xr1.w);
            za += __shfl_xor_sync(FULLM, za, 1);
            za += __shfl_xor_sync(FULLM, za, 2);
            za += __shfl_xor_sync(FULLM, za, 4);
            float mn = fmaxf(m, za);
            float pa = __expf(za - mn);
            if (mn == m) {
                den += pa;
                a0.x += pa * u0.x; a0.y += pa * u0.y; a0.z += pa * u0.z; a0.w += pa * u0.w;
                a1.x += pa * u1.x; a1.y += pa * u1.y; a1.z += pa * u1.z; a1.w += pa * u1.w;
            } else {
                float sc = __expf(m - mn);
                den = den * sc + pa;
                a0.x = a0.x * sc + pa * u0.x; a0.y = a0.y * sc + pa * u0.y;
                a0.z = a0.z * sc + pa * u0.z; a0.w = a0.w * sc + pa * u0.w;
                a1.x = a1.x * sc + pa * u1.x; a1.y = a1.y * sc + pa * u1.y;
                a1.z = a1.z * sc + pa * u1.z; a1.w = a1.w * sc + pa * u1.w;
                m = mn;
            }
        }
    }

    float inv = __frcp_rn(den);
    float v[8] = { a0.x * inv, a0.y * inv, a0.z * inv, a0.w * inv,
                   a1.x * inv, a1.y * inv, a1.z * inv, a1.w * inv };

    // sum across heads (lanes differing in bits 3,4)
    #pragma unroll
    for (int k = 0; k < 8; k++) {
        v[k] += __shfl_xor_sync(FULLM, v[k], 8);
        v[k] += __shfl_xor_sync(FULLM, v[k], 16);
    }

    // epilogue: mean, +bgat, relu, dot with Wlin
    int c = (lane & 7) * 8;
    float sc = 0.f;
    #pragma unroll
    for (int k = 0; k < 8; k++) {
        float hv = fmaxf(0.25f * v[k] + __ldg(&bgat[c + k]), 0.f);
        sc += hv * __ldg(&Wlin[c + k]);
    }
    sc += __shfl_xor_sync(FULLM, sc, 1);
    sc += __shfl_xor_sync(FULLM, sc, 2);
    sc += __shfl_xor_sync(FULLM, sc, 4);
    if (lane == 0) out[node] = sc + __ldg(&blin[0]);
}

// ---------------- launch ----------------
extern "C" void kernel_launch(void* const* d_in, const int* in_sizes, int n_in,
                              void* d_out, int out_size) {
    const float* x    = (const float*)d_in[0];
    const int*   ei   = (const int*)d_in[1];
    // d_in[2] = edge_attr (unused by reference)
    const float* Wg   = (const float*)d_in[3];
    const float* bg   = (const float*)d_in[4];
    const float* Wl   = (const float*)d_in[5];
    const float* bl   = (const float*)d_in[6];
    const float* Wr   = (const float*)d_in[7];
    const float* br   = (const float*)d_in[8];
    const float* att  = (const float*)d_in[9];
    const float* bgat = (const float*)d_in[10];
    const float* Wlin = (const float*)d_in[11];
    const float* blin = (const float*)d_in[12];
    float* out = (float*)d_out;

    int n = in_sizes[0] / IND;       // 50000
    int e = in_sizes[1] / 2;         // 800000
    const int* src = ei;
    const int* dst = ei + e;
    int nblk = (n + 1023) / 1024;    // 49

    // created once (first, non-captured correctness call); reused thereafter
    static cudaStream_t s2 = nullptr;
    static cudaEvent_t ev1 = nullptr, ev2 = nullptr;
    if (!s2) {
        cudaStreamCreateWithFlags(&s2, cudaStreamNonBlocking);
        cudaEventCreateWithFlags(&ev1, cudaEventDisableTiming);
        cudaEventCreateWithFlags(&ev2, cudaEventDisableTiming);
    }

    // fork: GEMM1 (independent of CSR) on s2
    cudaEventRecord(ev1, 0);
    cudaStreamWaitEvent(s2, ev1, 0);
    k_gemm1<<<(n + 63) / 64, 256, 0, s2>>>(x, Wg, n);
    cudaEventRecord(ev2, s2);

    // CSR build on stream 0
    k_init <<<(n + 255) / 256, 256>>>(n);
    k_hist <<<(e + 255) / 256, 256>>>(dst, e);
    k_scan1<<<nblk, 1024>>>(n);
    k_scan2<<<1, 64>>>(nblk);
    k_scan3<<<(n + 255) / 256, 256>>>(n, e);
    k_fill <<<(e + 255) / 256, 256>>>(src, dst, e);

    // join: gcn needs g_xw + CSR
    cudaStreamWaitEvent(0, ev2, 0);
    k_gcn  <<<(n * 32 + 255) / 256, 256>>>(bg, n);

    dim3 g2((n + 63) / 64, 8);
    k_gemm2<<<g2, 256>>>(Wl, bl, Wr, br, n);

    k_gat  <<<(n * 32 + 255) / 256, 256>>>(att, bgat, Wlin, blin, out, n);
}